// round 2
// baseline (speedup 1.0000x reference)
#include <cuda_runtime.h>
#include <math.h>

#define N_NODES  100000
#define N_EDGES  1000000
#define IN_CH    64
#define HID      128
#define N_GRAPHS 256
#define SCAN_B   ((N_NODES + 1023) / 1024)   // 98

// ---------------- scratch (static device globals; no allocation) ----------------
__device__ int   g_deg[N_NODES];
__device__ int   g_offs[N_NODES + 1];
__device__ int   g_bsum[128];
__device__ int   g_cur[N_NODES];
__device__ int   g_csr[N_EDGES];
__device__ float g_agg[(size_t)N_NODES * HID];   // conv1 uses first N*64
__device__ float g_h1[(size_t)N_NODES * HID];
__device__ float g_pooled[N_GRAPHS * HID];
__device__ float g_cnt[N_GRAPHS];

// ---------------- init ----------------
__global__ void zero_k() {
    int i = blockIdx.x * blockDim.x + threadIdx.x;
    if (i < N_NODES) g_deg[i] = 0;
    if (i < N_GRAPHS * HID) g_pooled[i] = 0.f;
    if (i < N_GRAPHS) g_cnt[i] = 0.f;
}

// ---------------- CSR build ----------------
__global__ void count_k(const int* __restrict__ ei) {
    int e = blockIdx.x * blockDim.x + threadIdx.x;
    if (e < N_EDGES) atomicAdd(&g_deg[ei[N_EDGES + e]], 1);
}

__global__ void batchcnt_k(const int* __restrict__ batch) {
    int i = blockIdx.x * blockDim.x + threadIdx.x;
    if (i < N_NODES) atomicAdd(&g_cnt[batch[i]], 1.f);
}

__global__ void scan1_k() {
    __shared__ int s[1024];
    int i = blockIdx.x * 1024 + threadIdx.x;
    int v = (i < N_NODES) ? g_deg[i] : 0;
    s[threadIdx.x] = v;
    __syncthreads();
    #pragma unroll
    for (int off = 1; off < 1024; off <<= 1) {
        int t = (threadIdx.x >= off) ? s[threadIdx.x - off] : 0;
        __syncthreads();
        s[threadIdx.x] += t;
        __syncthreads();
    }
    if (i < N_NODES) g_offs[i] = s[threadIdx.x] - v;   // exclusive
    if (threadIdx.x == 1023) g_bsum[blockIdx.x] = s[1023];
}

__global__ void scan2_k() {
    if (threadIdx.x == 0) {
        int run = 0;
        for (int b = 0; b < SCAN_B; b++) { int t = g_bsum[b]; g_bsum[b] = run; run += t; }
    }
}

__global__ void scan3_k() {
    int i = blockIdx.x * blockDim.x + threadIdx.x;
    if (i < N_NODES) {
        int v = g_offs[i] + g_bsum[i >> 10];
        g_offs[i] = v;
        g_cur[i]  = v;
    }
    if (i == 0) g_offs[N_NODES] = N_EDGES;
}

__global__ void scatter_k(const int* __restrict__ ei) {
    int e = blockIdx.x * blockDim.x + threadIdx.x;
    if (e < N_EDGES) {
        int d = ei[N_EDGES + e];
        int slot = atomicAdd(&g_cur[d], 1);
        g_csr[slot] = ei[e];
    }
}

// ---------------- mean aggregation (warp per node, CSR gather) ----------------
template<int D, bool FROM_H1>
__global__ void agg_k(const float* __restrict__ xin) {
    const float* __restrict__ feat = FROM_H1 ? (const float*)g_h1 : xin;
    int warp = (blockIdx.x * blockDim.x + threadIdx.x) >> 5;
    int lane = threadIdx.x & 31;
    if (warp >= N_NODES) return;
    int beg = g_offs[warp];
    int end = g_offs[warp + 1];
    float acc[D / 32];
    #pragma unroll
    for (int c = 0; c < D / 32; c++) acc[c] = 0.f;

    int j = beg;
    int s_next = (j < end) ? g_csr[j] : 0;
    for (; j < end; j++) {
        int s = s_next;
        s_next = (j + 1 < end) ? g_csr[j + 1] : 0;
        const float* row = feat + (size_t)s * D;
        #pragma unroll
        for (int c = 0; c < D / 32; c++) acc[c] += __ldg(row + c * 32 + lane);
    }
    float inv = 1.f / (float)max(end - beg, 1);
    #pragma unroll
    for (int c = 0; c < D / 32; c++)
        g_agg[(size_t)warp * D + c * 32 + lane] = acc[c] * inv;
}

// ---------------- fused SAGE matmul: relu(agg*Wa^T + B*Wb^T + bias) ----------------
// TM=128 nodes x TO=128 outs per block, 256 threads, 8x8 thread tile, KK=32.
// A = g_agg (always). B = x (conv1) or g_h1 (conv2).
// mode 0: write h to g_h1. mode 1: relu + atomicAdd into g_pooled[batch].
template<bool B_FROM_H1>
__global__ __launch_bounds__(256, 2) void mm_k(
    const float* __restrict__ xB,
    const float* __restrict__ Wa, int Ka,
    const float* __restrict__ Wb, int Kb,
    const float* __restrict__ bias,
    const int* __restrict__ batch, int mode)
{
    const int TM = 128, TO = 128, KK = 32;
    __shared__ __align__(16) float Ws[KK * TO];   // [k][o]
    __shared__ __align__(16) float As[KK * TM];   // [k][n]
    const float* __restrict__ A = (const float*)g_agg;
    const float* __restrict__ B = B_FROM_H1 ? (const float*)g_h1 : xB;

    int tid = threadIdx.x;
    int nbase = blockIdx.x * TM;
    int og = (tid & 15) * 8;
    int ng = (tid >> 4) * 8;
    float acc[8][8];
    #pragma unroll
    for (int i = 0; i < 8; i++)
        #pragma unroll
        for (int j = 0; j < 8; j++) acc[i][j] = 0.f;

    #pragma unroll 1
    for (int ph = 0; ph < 2; ph++) {
        const float* M = ph ? B : A;
        const float* W = ph ? Wb : Wa;
        int K = ph ? Kb : Ka;
        #pragma unroll 1
        for (int kb = 0; kb < K; kb += KK) {
            __syncthreads();
            // W tile: read W[o][kb+kq*4..+3] (float4), store transposed [k][o].
            #pragma unroll
            for (int i = 0; i < 4; i++) {
                int f = tid + i * 256;
                int o = f & 127, kq = f >> 7;
                const float4 w4 = *(const float4*)(W + (size_t)o * K + kb + kq * 4);
                Ws[(kq * 4 + 0) * TO + o] = w4.x;
                Ws[(kq * 4 + 1) * TO + o] = w4.y;
                Ws[(kq * 4 + 2) * TO + o] = w4.z;
                Ws[(kq * 4 + 3) * TO + o] = w4.w;
            }
            // A tile: same pattern, store transposed [k][n].
            #pragma unroll
            for (int i = 0; i < 4; i++) {
                int f = tid + i * 256;
                int n = f & 127, kq = f >> 7;
                int row = nbase + n;
                float4 a4 = make_float4(0.f, 0.f, 0.f, 0.f);
                if (row < N_NODES)
                    a4 = *(const float4*)(M + (size_t)row * K + kb + kq * 4);
                As[(kq * 4 + 0) * TM + n] = a4.x;
                As[(kq * 4 + 1) * TM + n] = a4.y;
                As[(kq * 4 + 2) * TM + n] = a4.z;
                As[(kq * 4 + 3) * TM + n] = a4.w;
            }
            __syncthreads();
            #pragma unroll
            for (int k = 0; k < KK; k++) {
                float4 a0 = *(const float4*)(As + k * TM + ng);
                float4 a1 = *(const float4*)(As + k * TM + ng + 4);
                float4 w0 = *(const float4*)(Ws + k * TO + og);
                float4 w1 = *(const float4*)(Ws + k * TO + og + 4);
                float av[8] = {a0.x, a0.y, a0.z, a0.w, a1.x, a1.y, a1.z, a1.w};
                float wv[8] = {w0.x, w0.y, w0.z, w0.w, w1.x, w1.y, w1.z, w1.w};
                #pragma unroll
                for (int ii = 0; ii < 8; ii++)
                    #pragma unroll
                    for (int jj = 0; jj < 8; jj++)
                        acc[ii][jj] += av[ii] * wv[jj];
            }
        }
    }

    if (mode == 0) {
        #pragma unroll
        for (int ii = 0; ii < 8; ii++) {
            int row = nbase + ng + ii;
            if (row < N_NODES) {
                #pragma unroll
                for (int jj = 0; jj < 8; jj++) {
                    float v = fmaxf(acc[ii][jj] + bias[og + jj], 0.f);
                    g_h1[(size_t)row * TO + og + jj] = v;
                }
            }
        }
    } else {
        #pragma unroll
        for (int ii = 0; ii < 8; ii++) {
            int row = nbase + ng + ii;
            if (row < N_NODES) {
                int g = batch[row];
                #pragma unroll
                for (int jj = 0; jj < 8; jj++) {
                    float v = fmaxf(acc[ii][jj] + bias[og + jj], 0.f);
                    atomicAdd(&g_pooled[g * HID + og + jj], v);
                }
            }
        }
    }
}

// ---------------- head: mean pool normalize + linear + log_softmax ----------------
__global__ void final_k(const float* __restrict__ Wout,
                        const float* __restrict__ bout,
                        float* __restrict__ out) {
    int g = threadIdx.x;
    if (g >= N_GRAPHS) return;
    float inv = 1.f / fmaxf(g_cnt[g], 1.f);
    float l0 = bout[0], l1 = bout[1];
    #pragma unroll 4
    for (int o = 0; o < HID; o++) {
        float p = g_pooled[g * HID + o] * inv;
        l0 += p * Wout[o];
        l1 += p * Wout[HID + o];
    }
    float m = fmaxf(l0, l1);
    float lse = m + logf(expf(l0 - m) + expf(l1 - m));
    out[g * 2 + 0] = l0 - lse;
    out[g * 2 + 1] = l1 - lse;
}

// ---------------- launch ----------------
extern "C" void kernel_launch(void* const* d_in, const int* in_sizes, int n_in,
                              void* d_out, int out_size) {
    const float* x     = (const float*)d_in[0];
    const int*   ei    = (const int*)d_in[1];
    const int*   batch = (const int*)d_in[2];
    const float* Wl1   = (const float*)d_in[3];
    const float* bl1   = (const float*)d_in[4];
    const float* Wr1   = (const float*)d_in[5];
    const float* Wl2   = (const float*)d_in[6];
    const float* bl2   = (const float*)d_in[7];
    const float* Wr2   = (const float*)d_in[8];
    const float* Wout  = (const float*)d_in[9];
    const float* bout  = (const float*)d_in[10];
    float* out = (float*)d_out;

    zero_k<<<(N_NODES + 255) / 256, 256>>>();
    count_k<<<(N_EDGES + 255) / 256, 256>>>(ei);
    batchcnt_k<<<(N_NODES + 255) / 256, 256>>>(batch);
    scan1_k<<<SCAN_B, 1024>>>();
    scan2_k<<<1, 32>>>();
    scan3_k<<<(N_NODES + 255) / 256, 256>>>();
    scatter_k<<<(N_EDGES + 255) / 256, 256>>>(ei);

    // conv1: agg = mean(x[src]) -> h1 = relu(agg*Wl1^T + x*Wr1^T + bl1)
    agg_k<IN_CH, false><<<(N_NODES + 7) / 8, 256>>>(x);
    mm_k<false><<<(N_NODES + 127) / 128, 256>>>(x, Wl1, IN_CH, Wr1, IN_CH, bl1, batch, 0);

    // conv2: agg2 = mean(h1[src]) -> h2 = relu(agg2*Wl2^T + h1*Wr2^T + bl2), pooled on the fly
    agg_k<HID, true><<<(N_NODES + 7) / 8, 256>>>(x);
    mm_k<true><<<(N_NODES + 127) / 128, 256>>>(x, Wl2, HID, Wr2, HID, bl2, batch, 1);

    final_k<<<1, 256>>>(Wout, bout, out);
}

// round 4
// speedup vs baseline: 1.8170x; 1.8170x over previous
#include <cuda_runtime.h>
#include <math.h>
#include <stdint.h>

#define N_NODES  100000
#define N_EDGES  1000000
#define IN_CH    64
#define HID      128
#define N_GRAPHS 256
#define SCAN_B   ((N_NODES + 1023) / 1024)   // 98

// ---------------- scratch (static device globals; no allocation) ----------------
__device__ int   g_deg[N_NODES];
__device__ int   g_offs[N_NODES + 1];
__device__ int   g_bsum[128];
__device__ int   g_cur[N_NODES];
__device__ int   g_csr[N_EDGES];
__device__ float g_agg[(size_t)N_NODES * HID];   // conv1 uses first N*64
__device__ float g_h1[(size_t)N_NODES * HID];
__device__ float g_h2[(size_t)N_NODES * HID];
__device__ float g_pooled[N_GRAPHS * HID];
__device__ float g_cnt[N_GRAPHS];

__device__ __forceinline__ uint32_t f2tf(float f) {
    uint32_t u;
    asm("cvt.rna.tf32.f32 %0, %1;" : "=r"(u) : "f"(f));
    return u;
}
__device__ __forceinline__ void mma_tf32(float* c, const uint32_t* a, const uint32_t* b) {
    asm volatile(
        "mma.sync.aligned.m16n8k8.row.col.f32.tf32.tf32.f32 "
        "{%0,%1,%2,%3}, {%4,%5,%6,%7}, {%8,%9}, {%0,%1,%2,%3};"
        : "+f"(c[0]), "+f"(c[1]), "+f"(c[2]), "+f"(c[3])
        : "r"(a[0]), "r"(a[1]), "r"(a[2]), "r"(a[3]), "r"(b[0]), "r"(b[1]));
}

// ---------------- init ----------------
__global__ void zero_k() {
    int i = blockIdx.x * blockDim.x + threadIdx.x;
    if (i < N_NODES) g_deg[i] = 0;
}

// ---------------- CSR build ----------------
__global__ void count_k(const int* __restrict__ ei) {
    int e = blockIdx.x * blockDim.x + threadIdx.x;
    if (e < N_EDGES) atomicAdd(&g_deg[ei[N_EDGES + e]], 1);
}

__global__ void scan1_k() {
    __shared__ int s[1024];
    int i = blockIdx.x * 1024 + threadIdx.x;
    int v = (i < N_NODES) ? g_deg[i] : 0;
    s[threadIdx.x] = v;
    __syncthreads();
    #pragma unroll
    for (int off = 1; off < 1024; off <<= 1) {
        int t = (threadIdx.x >= off) ? s[threadIdx.x - off] : 0;
        __syncthreads();
        s[threadIdx.x] += t;
        __syncthreads();
    }
    if (i < N_NODES) g_offs[i] = s[threadIdx.x] - v;   // exclusive
    if (threadIdx.x == 1023) g_bsum[blockIdx.x] = s[1023];
}

__global__ void scan2_k() {
    if (threadIdx.x == 0) {
        int run = 0;
        for (int b = 0; b < SCAN_B; b++) { int t = g_bsum[b]; g_bsum[b] = run; run += t; }
    }
}

__global__ void scan3_k() {
    int i = blockIdx.x * blockDim.x + threadIdx.x;
    if (i < N_NODES) {
        int v = g_offs[i] + g_bsum[i >> 10];
        g_offs[i] = v;
        g_cur[i]  = v;
    }
    if (i == 0) g_offs[N_NODES] = N_EDGES;
}

__global__ void scatter_k(const int* __restrict__ ei) {
    int e = blockIdx.x * blockDim.x + threadIdx.x;
    if (e < N_EDGES) {
        int d = ei[N_EDGES + e];
        int slot = atomicAdd(&g_cur[d], 1);
        g_csr[slot] = ei[e];
    }
}

// ---------------- mean aggregation (warp per node, CSR gather) ----------------
template<int D, bool FROM_H1>
__global__ void agg_k(const float* __restrict__ xin) {
    const float* __restrict__ feat = FROM_H1 ? (const float*)g_h1 : xin;
    int warp = (blockIdx.x * blockDim.x + threadIdx.x) >> 5;
    int lane = threadIdx.x & 31;
    if (warp >= N_NODES) return;
    int beg = g_offs[warp];
    int end = g_offs[warp + 1];
    float acc[D / 32];
    #pragma unroll
    for (int c = 0; c < D / 32; c++) acc[c] = 0.f;

    int j = beg;
    int s_next = (j < end) ? g_csr[j] : 0;
    for (; j < end; j++) {
        int s = s_next;
        s_next = (j + 1 < end) ? g_csr[j + 1] : 0;
        const float* row = feat + (size_t)s * D;
        #pragma unroll
        for (int c = 0; c < D / 32; c++) acc[c] += __ldg(row + c * 32 + lane);
    }
    float inv = 1.f / (float)max(end - beg, 1);
    #pragma unroll
    for (int c = 0; c < D / 32; c++)
        g_agg[(size_t)warp * D + c * 32 + lane] = acc[c] * inv;
}

// ---------------- tf32 mma.sync fused SAGE matmul ----------------
// Per block: 128 nodes (M) x 128 outs (N). D = relu(agg*Wa^T + B*Wb^T + bias).
// 8 warps in 2(M) x 4(N): warp tile 64x32 = 4x4 mma tiles of m16n8k8.
// Smem tiles: [row][36] stride (conflict-free fragment LDS: bank = 4*g + tig).
// MODE 0 -> g_h1, MODE 1 -> g_h2.
#define SSTR 36
template<bool B_FROM_H1, int MODE>
__global__ __launch_bounds__(256) void mm_mma(
    const float* __restrict__ xB,
    const float* __restrict__ Wa, int Ka,
    const float* __restrict__ Wb, int Kb,
    const float* __restrict__ bias)
{
    __shared__ __align__(16) uint32_t sA[128 * SSTR];  // node tile [m][k]
    __shared__ __align__(16) uint32_t sW[128 * SSTR];  // weight tile [o][k]
    __shared__ float sBias[128];

    const float* __restrict__ A = (const float*)g_agg;
    const float* __restrict__ B = B_FROM_H1 ? (const float*)g_h1 : xB;

    int tid = threadIdx.x, wid = tid >> 5, lane = tid & 31;
    int g = lane >> 2, tig = lane & 3;
    int warp_m = (wid & 1) * 64;
    int warp_n = (wid >> 1) * 32;
    int nbase = blockIdx.x * 128;

    if (tid < 128) sBias[tid] = bias[tid];

    float acc[4][4][4];
    #pragma unroll
    for (int mt = 0; mt < 4; mt++)
        #pragma unroll
        for (int nt = 0; nt < 4; nt++)
            #pragma unroll
            for (int r = 0; r < 4; r++) acc[mt][nt][r] = 0.f;

    #pragma unroll 1
    for (int ph = 0; ph < 2; ph++) {
        const float* M = ph ? B : A;
        const float* W = ph ? Wb : Wa;
        int K = ph ? Kb : Ka;
        #pragma unroll 1
        for (int kb = 0; kb < K; kb += 32) {
            __syncthreads();
            // stage: 128 rows x 32 cols each of M and W; 4 float4 per thread per matrix
            #pragma unroll
            for (int i = 0; i < 4; i++) {
                int f = tid + i * 256;
                int row = f >> 3, c4 = (f & 7) * 4;
                int grow = nbase + row;
                float4 a = make_float4(0.f, 0.f, 0.f, 0.f);
                if (grow < N_NODES)
                    a = *(const float4*)(M + (size_t)grow * K + kb + c4);
                uint32_t* pa = &sA[row * SSTR + c4];
                pa[0] = f2tf(a.x); pa[1] = f2tf(a.y); pa[2] = f2tf(a.z); pa[3] = f2tf(a.w);
                float4 w = *(const float4*)(W + (size_t)row * K + kb + c4);
                uint32_t* pw = &sW[row * SSTR + c4];
                pw[0] = f2tf(w.x); pw[1] = f2tf(w.y); pw[2] = f2tf(w.z); pw[3] = f2tf(w.w);
            }
            __syncthreads();
            #pragma unroll
            for (int ks = 0; ks < 4; ks++) {
                int k0 = ks * 8;
                uint32_t af[4][4], bf[4][2];
                #pragma unroll
                for (int mt = 0; mt < 4; mt++) {
                    int r0 = warp_m + mt * 16;
                    af[mt][0] = sA[(r0 + g) * SSTR + k0 + tig];
                    af[mt][1] = sA[(r0 + g + 8) * SSTR + k0 + tig];
                    af[mt][2] = sA[(r0 + g) * SSTR + k0 + tig + 4];
                    af[mt][3] = sA[(r0 + g + 8) * SSTR + k0 + tig + 4];
                }
                #pragma unroll
                for (int nt = 0; nt < 4; nt++) {
                    int c0 = warp_n + nt * 8;
                    bf[nt][0] = sW[(c0 + g) * SSTR + k0 + tig];
                    bf[nt][1] = sW[(c0 + g) * SSTR + k0 + tig + 4];
                }
                #pragma unroll
                for (int mt = 0; mt < 4; mt++)
                    #pragma unroll
                    for (int nt = 0; nt < 4; nt++)
                        mma_tf32(acc[mt][nt], af[mt], bf[nt]);
            }
        }
    }

    // epilogue: bias + relu, write float2 pairs
    float* dst = (MODE == 0) ? (float*)g_h1 : (float*)g_h2;
    #pragma unroll
    for (int mt = 0; mt < 4; mt++) {
        #pragma unroll
        for (int half = 0; half < 2; half++) {
            int row = nbase + warp_m + mt * 16 + g + half * 8;
            if (row < N_NODES) {
                float* drow = dst + (size_t)row * HID;
                #pragma unroll
                for (int nt = 0; nt < 4; nt++) {
                    int col = warp_n + nt * 8 + 2 * tig;
                    float2 v;
                    v.x = fmaxf(acc[mt][nt][half * 2 + 0] + sBias[col + 0], 0.f);
                    v.y = fmaxf(acc[mt][nt][half * 2 + 1] + sBias[col + 1], 0.f);
                    *(float2*)(drow + col) = v;
                }
            }
        }
    }
}

// ---------------- per-graph mean pool (batch is sorted) ----------------
__global__ void pool_k(const int* __restrict__ batch) {
    int g = blockIdx.x;
    __shared__ int s_lo, s_hi;
    if (threadIdx.x == 0) {
        int a = 0, b = N_NODES;
        while (a < b) { int m = (a + b) >> 1; if (batch[m] < g) a = m + 1; else b = m; }
        s_lo = a;
        b = N_NODES;
        while (a < b) { int m = (a + b) >> 1; if (batch[m] < g + 1) a = m + 1; else b = m; }
        s_hi = a;
    }
    __syncthreads();
    int lo = s_lo, hi = s_hi;
    int col = threadIdx.x;   // 128 threads, one col each
    float acc = 0.f;
    int r = lo;
    for (; r + 4 <= hi; r += 4) {
        float v0 = g_h2[(size_t)(r + 0) * HID + col];
        float v1 = g_h2[(size_t)(r + 1) * HID + col];
        float v2 = g_h2[(size_t)(r + 2) * HID + col];
        float v3 = g_h2[(size_t)(r + 3) * HID + col];
        acc += (v0 + v1) + (v2 + v3);
    }
    for (; r < hi; r++) acc += g_h2[(size_t)r * HID + col];
    g_pooled[g * HID + col] = acc;
    if (threadIdx.x == 0) g_cnt[g] = (float)(hi - lo);
}

// ---------------- head: normalize + linear + log_softmax ----------------
__global__ void final_k(const float* __restrict__ Wout,
                        const float* __restrict__ bout,
                        float* __restrict__ out) {
    int g = threadIdx.x + blockIdx.x * blockDim.x;
    if (g >= N_GRAPHS) return;
    float inv = 1.f / fmaxf(g_cnt[g], 1.f);
    float l0 = bout[0], l1 = bout[1];
    #pragma unroll 4
    for (int o = 0; o < HID; o++) {
        float p = g_pooled[g * HID + o] * inv;
        l0 += p * Wout[o];
        l1 += p * Wout[HID + o];
    }
    float m = fmaxf(l0, l1);
    float lse = m + logf(expf(l0 - m) + expf(l1 - m));
    out[g * 2 + 0] = l0 - lse;
    out[g * 2 + 1] = l1 - lse;
}

// ---------------- launch ----------------
extern "C" void kernel_launch(void* const* d_in, const int* in_sizes, int n_in,
                              void* d_out, int out_size) {
    const float* x     = (const float*)d_in[0];
    const int*   ei    = (const int*)d_in[1];
    const int*   batch = (const int*)d_in[2];
    const float* Wl1   = (const float*)d_in[3];
    const float* bl1   = (const float*)d_in[4];
    const float* Wr1   = (const float*)d_in[5];
    const float* Wl2   = (const float*)d_in[6];
    const float* bl2   = (const float*)d_in[7];
    const float* Wr2   = (const float*)d_in[8];
    const float* Wout  = (const float*)d_in[9];
    const float* bout  = (const float*)d_in[10];
    float* out = (float*)d_out;

    zero_k<<<(N_NODES + 255) / 256, 256>>>();
    count_k<<<(N_EDGES + 255) / 256, 256>>>(ei);
    scan1_k<<<SCAN_B, 1024>>>();
    scan2_k<<<1, 32>>>();
    scan3_k<<<(N_NODES + 255) / 256, 256>>>();
    scatter_k<<<(N_EDGES + 255) / 256, 256>>>(ei);

    const int MMG = (N_NODES + 127) / 128;
    // conv1
    agg_k<IN_CH, false><<<(N_NODES + 7) / 8, 256>>>(x);
    mm_mma<false, 0><<<MMG, 256>>>(x, Wl1, IN_CH, Wr1, IN_CH, bl1);
    // conv2
    agg_k<HID, true><<<(N_NODES + 7) / 8, 256>>>(x);
    mm_mma<true, 1><<<MMG, 256>>>(x, Wl2, HID, Wr2, HID, bl2);

    pool_k<<<N_GRAPHS, 128>>>(batch);
    final_k<<<1, 256>>>(Wout, bout, out);
}

// round 6
// speedup vs baseline: 2.2375x; 1.2314x over previous
#include <cuda_runtime.h>
#include <math.h>
#include <stdint.h>

#define N_NODES  100000
#define N_EDGES  1000000
#define IN_CH    64
#define HID      128
#define N_GRAPHS 256
#define SCAN_B   ((N_NODES + 1023) / 1024)   // 98

// ---------------- scratch (static device globals; no allocation) ----------------
__device__ int   g_deg[N_NODES];
__device__ int   g_offs[N_NODES + 1];
__device__ int   g_bsum[128];
__device__ int   g_cur[N_NODES];
__device__ int   g_csr[N_EDGES];
__device__ __align__(16) float g_agg[(size_t)N_NODES * HID];  // tf32-valued
__device__ __align__(16) float g_h1[(size_t)N_NODES * HID];   // tf32-valued
__device__ __align__(16) float g_h2[(size_t)N_NODES * HID];
__device__ __align__(16) float g_xtf[(size_t)N_NODES * IN_CH];
__device__ __align__(16) float g_wl1[HID * IN_CH];
__device__ __align__(16) float g_wr1[HID * IN_CH];
__device__ __align__(16) float g_wl2[HID * HID];
__device__ __align__(16) float g_wr2[HID * HID];
__device__ float g_pooled[N_GRAPHS * HID];
__device__ float g_cnt[N_GRAPHS];

// ---------------- helpers ----------------
__device__ __forceinline__ uint32_t smem_u32(const void* p) {
    uint32_t a;
    asm("{ .reg .u64 t; cvta.to.shared.u64 t, %1; cvt.u32.u64 %0, t; }" : "=r"(a) : "l"(p));
    return a;
}
__device__ __forceinline__ uint32_t f2tf(float f) {
    uint32_t u;
    asm("cvt.rna.tf32.f32 %0, %1;" : "=r"(u) : "f"(f));
    return u;
}
__device__ __forceinline__ float tfv(float f) { return __uint_as_float(f2tf(f)); }

__device__ __forceinline__ void mma_tf32(float* c, const uint32_t* a, const uint32_t* b) {
    asm volatile(
        "mma.sync.aligned.m16n8k8.row.col.f32.tf32.tf32.f32 "
        "{%0,%1,%2,%3}, {%4,%5,%6,%7}, {%8,%9}, {%0,%1,%2,%3};"
        : "+f"(c[0]), "+f"(c[1]), "+f"(c[2]), "+f"(c[3])
        : "r"(a[0]), "r"(a[1]), "r"(a[2]), "r"(a[3]), "r"(b[0]), "r"(b[1]));
}
__device__ __forceinline__ void cp16(uint32_t dst, const void* src) {
    asm volatile("cp.async.cg.shared.global [%0], [%1], 16;" :: "r"(dst), "l"(src));
}
__device__ __forceinline__ void cp16p(uint32_t dst, const void* src, bool full) {
    int sz = full ? 16 : 0;
    asm volatile("cp.async.cg.shared.global [%0], [%1], 16, %2;" :: "r"(dst), "l"(src), "r"(sz));
}
#define CP_COMMIT() asm volatile("cp.async.commit_group;" ::: "memory")
#define CP_WAIT1()  asm volatile("cp.async.wait_group 1;" ::: "memory")
#define CP_WAIT0()  asm volatile("cp.async.wait_group 0;" ::: "memory")

// ---------------- init / CSR build ----------------
__global__ void zero_k() {
    int i = blockIdx.x * blockDim.x + threadIdx.x;
    if (i < N_NODES) g_deg[i] = 0;
}

__global__ void count_k(const int* __restrict__ ei) {
    int e = blockIdx.x * blockDim.x + threadIdx.x;
    if (e < N_EDGES) atomicAdd(&g_deg[ei[N_EDGES + e]], 1);
}

__global__ void scan1_k() {
    __shared__ int s[1024];
    int i = blockIdx.x * 1024 + threadIdx.x;
    int v = (i < N_NODES) ? g_deg[i] : 0;
    s[threadIdx.x] = v;
    __syncthreads();
    #pragma unroll
    for (int off = 1; off < 1024; off <<= 1) {
        int t = (threadIdx.x >= off) ? s[threadIdx.x - off] : 0;
        __syncthreads();
        s[threadIdx.x] += t;
        __syncthreads();
    }
    if (i < N_NODES) g_offs[i] = s[threadIdx.x] - v;   // exclusive
    if (threadIdx.x == 1023) g_bsum[blockIdx.x] = s[1023];
}

__global__ void scan2_k() {   // parallel 128-wide scan over SCAN_B block sums
    __shared__ int s[128];
    int t = threadIdx.x;
    int v = (t < SCAN_B) ? g_bsum[t] : 0;
    s[t] = v;
    __syncthreads();
    #pragma unroll
    for (int off = 1; off < 128; off <<= 1) {
        int u = (t >= off) ? s[t - off] : 0;
        __syncthreads();
        s[t] += u;
        __syncthreads();
    }
    if (t < SCAN_B) g_bsum[t] = s[t] - v;   // exclusive
}

__global__ void scan3_k() {
    int i = blockIdx.x * blockDim.x + threadIdx.x;
    if (i < N_NODES) {
        int v = g_offs[i] + g_bsum[i >> 10];
        g_offs[i] = v;
        g_cur[i]  = v;
    }
    if (i == 0) g_offs[N_NODES] = N_EDGES;
}

__global__ void scatter_k(const int* __restrict__ ei) {
    int e = blockIdx.x * blockDim.x + threadIdx.x;
    if (e < N_EDGES) {
        int d = ei[N_EDGES + e];
        int slot = atomicAdd(&g_cur[d], 1);
        g_csr[slot] = ei[e];
    }
}

// ---------------- tf32 pre-rounding of GEMM inputs ----------------
__global__ void xcvt_k(const float4* __restrict__ x) {
    int i = blockIdx.x * blockDim.x + threadIdx.x;
    if (i < N_NODES * IN_CH / 4) {
        float4 v = x[i];
        float4 o;
        o.x = tfv(v.x); o.y = tfv(v.y); o.z = tfv(v.z); o.w = tfv(v.w);
        *((float4*)g_xtf + i) = o;
    }
}

__global__ void wcvt_k(const float* __restrict__ wl1, const float* __restrict__ wr1,
                       const float* __restrict__ wl2, const float* __restrict__ wr2) {
    int i = blockIdx.x * blockDim.x + threadIdx.x;
    if (i < HID * IN_CH) { g_wl1[i] = tfv(wl1[i]); g_wr1[i] = tfv(wr1[i]); }
    if (i < HID * HID)   { g_wl2[i] = tfv(wl2[i]); g_wr2[i] = tfv(wr2[i]); }
}

// ---------------- mean aggregation (warp per node, vectorized CSR gather) -------
// stores tf32-rounded means
__global__ void agg64_k(const float* __restrict__ xin) {
    int node = (blockIdx.x * blockDim.x + threadIdx.x) >> 5;
    int lane = threadIdx.x & 31;
    if (node >= N_NODES) return;
    int beg = g_offs[node], end = g_offs[node + 1];
    float2 a0 = make_float2(0.f, 0.f), a1 = make_float2(0.f, 0.f);
    int j = beg;
    for (; j + 1 < end; j += 2) {
        int s0 = g_csr[j], s1 = g_csr[j + 1];
        float2 v0 = __ldg((const float2*)(xin + (size_t)s0 * IN_CH) + lane);
        float2 v1 = __ldg((const float2*)(xin + (size_t)s1 * IN_CH) + lane);
        a0.x += v0.x; a0.y += v0.y;
        a1.x += v1.x; a1.y += v1.y;
    }
    if (j < end) {
        int s0 = g_csr[j];
        float2 v0 = __ldg((const float2*)(xin + (size_t)s0 * IN_CH) + lane);
        a0.x += v0.x; a0.y += v0.y;
    }
    float inv = 1.f / (float)max(end - beg, 1);
    float2 o;
    o.x = tfv((a0.x + a1.x) * inv);
    o.y = tfv((a0.y + a1.y) * inv);
    *((float2*)(g_agg + (size_t)node * IN_CH) + lane) = o;
}

__global__ void agg128_k() {
    int node = (blockIdx.x * blockDim.x + threadIdx.x) >> 5;
    int lane = threadIdx.x & 31;
    if (node >= N_NODES) return;
    int beg = g_offs[node], end = g_offs[node + 1];
    float4 a0 = make_float4(0.f, 0.f, 0.f, 0.f), a1 = make_float4(0.f, 0.f, 0.f, 0.f);
    int j = beg;
    for (; j + 1 < end; j += 2) {
        int s0 = g_csr[j], s1 = g_csr[j + 1];
        float4 v0 = __ldg((const float4*)(g_h1 + (size_t)s0 * HID) + lane);
        float4 v1 = __ldg((const float4*)(g_h1 + (size_t)s1 * HID) + lane);
        a0.x += v0.x; a0.y += v0.y; a0.z += v0.z; a0.w += v0.w;
        a1.x += v1.x; a1.y += v1.y; a1.z += v1.z; a1.w += v1.w;
    }
    if (j < end) {
        int s0 = g_csr[j];
        float4 v0 = __ldg((const float4*)(g_h1 + (size_t)s0 * HID) + lane);
        a0.x += v0.x; a0.y += v0.y; a0.z += v0.z; a0.w += v0.w;
    }
    float inv = 1.f / (float)max(end - beg, 1);
    float4 o;
    o.x = tfv((a0.x + a1.x) * inv);
    o.y = tfv((a0.y + a1.y) * inv);
    o.z = tfv((a0.z + a1.z) * inv);
    o.w = tfv((a0.w + a1.w) * inv);
    *((float4*)(g_agg + (size_t)node * HID) + lane) = o;
}

// ---------------- tf32 mma.sync fused SAGE matmul (cp.async double-buffered) ----
// Per block: 128 nodes (M) x 128 outs (N). D = relu(agg*Wa^T + B*Wb^T + bias).
// 8 warps in 2(M) x 4(N): warp tile 64x32 = 4x4 mma tiles of m16n8k8.
// Inputs are pre-rounded tf32 values; staging is pure cp.async.
// Weight/feature buffers are __device__ symbols resolved IN DEVICE CODE via LAYER.
#define SSTR 36
#define MMTILE (128 * SSTR)        // words per matrix tile
#define MMBUF  (2 * MMTILE)        // words per buffer (A + W)
#define MM_SMEM (2 * MMBUF * 4)    // bytes (73728)

__device__ __forceinline__ void mm_stage(uint32_t sbase, int buf, int tid, int nbase,
                                         const float* M, const float* W, int K, int kb) {
    #pragma unroll
    for (int i = 0; i < 4; i++) {
        int f = tid + i * 256;
        int row = f >> 3, c4 = (f & 7) * 4;
        uint32_t da = sbase + (uint32_t)(buf * MMBUF + row * SSTR + c4) * 4u;
        int grow = nbase + row;
        cp16p(da, M + (size_t)grow * K + kb + c4, grow < N_NODES);
        cp16(da + MMTILE * 4u, W + (size_t)row * K + kb + c4);
    }
    CP_COMMIT();
}

__device__ __forceinline__ void mm_compute(const uint32_t* sbuf, int warp_m, int warp_n,
                                           int g, int tig, float acc[4][4][4]) {
    const uint32_t* sA = sbuf;
    const uint32_t* sW = sbuf + MMTILE;
    #pragma unroll
    for (int ks = 0; ks < 4; ks++) {
        int k0 = ks * 8;
        uint32_t af[4][4], bf[4][2];
        #pragma unroll
        for (int mt = 0; mt < 4; mt++) {
            int r0 = warp_m + mt * 16;
            af[mt][0] = sA[(r0 + g) * SSTR + k0 + tig];
            af[mt][1] = sA[(r0 + g + 8) * SSTR + k0 + tig];
            af[mt][2] = sA[(r0 + g) * SSTR + k0 + tig + 4];
            af[mt][3] = sA[(r0 + g + 8) * SSTR + k0 + tig + 4];
        }
        #pragma unroll
        for (int nt = 0; nt < 4; nt++) {
            int c0 = warp_n + nt * 8;
            bf[nt][0] = sW[(c0 + g) * SSTR + k0 + tig];
            bf[nt][1] = sW[(c0 + g) * SSTR + k0 + tig + 4];
        }
        #pragma unroll
        for (int mt = 0; mt < 4; mt++)
            #pragma unroll
            for (int nt = 0; nt < 4; nt++)
                mma_tf32(acc[mt][nt], af[mt], bf[nt]);
    }
}

template<int LAYER>
__global__ __launch_bounds__(256, 2) void mm_mma(const float* __restrict__ bias) {
    extern __shared__ uint32_t dsm[];
    __shared__ float sBias[128];

    // resolve all device symbols in device code (host symbol addresses are invalid!)
    const float* A  = (const float*)g_agg;
    const float* B  = (LAYER == 0) ? (const float*)g_xtf : (const float*)g_h1;
    const float* Wa = (LAYER == 0) ? (const float*)g_wl1 : (const float*)g_wl2;
    const float* Wb = (LAYER == 0) ? (const float*)g_wr1 : (const float*)g_wr2;
    constexpr int K = (LAYER == 0) ? IN_CH : HID;
    constexpr int nA = K / 32;
    constexpr int total = 2 * nA;
    float* dst = (LAYER == 0) ? (float*)g_h1 : (float*)g_h2;

    int tid = threadIdx.x, wid = tid >> 5, lane = tid & 31;
    int g = lane >> 2, tig = lane & 3;
    int warp_m = (wid & 1) * 64;
    int warp_n = (wid >> 1) * 32;
    int nbase = blockIdx.x * 128;
    uint32_t sbase = smem_u32(dsm);

    if (tid < 128) sBias[tid] = bias[tid];

    float acc[4][4][4];
    #pragma unroll
    for (int mt = 0; mt < 4; mt++)
        #pragma unroll
        for (int nt = 0; nt < 4; nt++)
            #pragma unroll
            for (int r = 0; r < 4; r++) acc[mt][nt][r] = 0.f;

    auto pick = [&](int c, const float*& M, const float*& W, int& kb) {
        if (c < nA) { M = A; W = Wa; kb = c * 32; }
        else        { M = B; W = Wb; kb = (c - nA) * 32; }
    };

    { const float* M; const float* W; int kb;
      pick(0, M, W, kb);
      mm_stage(sbase, 0, tid, nbase, M, W, K, kb); }

    #pragma unroll 1
    for (int c = 0; c < total; c++) {
        if (c + 1 < total) {
            const float* M; const float* W; int kb;
            pick(c + 1, M, W, kb);
            mm_stage(sbase, (c + 1) & 1, tid, nbase, M, W, K, kb);
            CP_WAIT1();
        } else {
            CP_WAIT0();
        }
        __syncthreads();
        mm_compute(dsm + (c & 1) * MMBUF, warp_m, warp_n, g, tig, acc);
        __syncthreads();
    }

    // epilogue: bias + relu; LAYER 0 stores tf32-rounded h1, LAYER 1 stores fp32 h2
    #pragma unroll
    for (int mt = 0; mt < 4; mt++) {
        #pragma unroll
        for (int half = 0; half < 2; half++) {
            int row = nbase + warp_m + mt * 16 + g + half * 8;
            if (row < N_NODES) {
                float* drow = dst + (size_t)row * HID;
                #pragma unroll
                for (int nt = 0; nt < 4; nt++) {
                    int col = warp_n + nt * 8 + 2 * tig;
                    float vx = fmaxf(acc[mt][nt][half * 2 + 0] + sBias[col + 0], 0.f);
                    float vy = fmaxf(acc[mt][nt][half * 2 + 1] + sBias[col + 1], 0.f);
                    float2 v;
                    if (LAYER == 0) { v.x = tfv(vx); v.y = tfv(vy); }
                    else            { v.x = vx;      v.y = vy; }
                    *(float2*)(drow + col) = v;
                }
            }
        }
    }
}

// ---------------- per-graph mean pool (batch is sorted) ----------------
__global__ void pool_k(const int* __restrict__ batch) {
    int g = blockIdx.x;
    __shared__ int s_lo, s_hi;
    if (threadIdx.x == 0) {
        int a = 0, b = N_NODES;
        while (a < b) { int m = (a + b) >> 1; if (batch[m] < g) a = m + 1; else b = m; }
        s_lo = a;
        b = N_NODES;
        while (a < b) { int m = (a + b) >> 1; if (batch[m] < g + 1) a = m + 1; else b = m; }
        s_hi = a;
    }
    __syncthreads();
    int lo = s_lo, hi = s_hi;
    int col = threadIdx.x;
    float acc = 0.f;
    int r = lo;
    for (; r + 4 <= hi; r += 4) {
        float v0 = g_h2[(size_t)(r + 0) * HID + col];
        float v1 = g_h2[(size_t)(r + 1) * HID + col];
        float v2 = g_h2[(size_t)(r + 2) * HID + col];
        float v3 = g_h2[(size_t)(r + 3) * HID + col];
        acc += (v0 + v1) + (v2 + v3);
    }
    for (; r < hi; r++) acc += g_h2[(size_t)r * HID + col];
    g_pooled[g * HID + col] = acc;
    if (threadIdx.x == 0) g_cnt[g] = (float)(hi - lo);
}

// ---------------- head: normalize + linear + log_softmax ----------------
__global__ void final_k(const float* __restrict__ Wout,
                        const float* __restrict__ bout,
                        float* __restrict__ out) {
    int g = threadIdx.x + blockIdx.x * blockDim.x;
    if (g >= N_GRAPHS) return;
    float inv = 1.f / fmaxf(g_cnt[g], 1.f);
    float l0 = bout[0], l1 = bout[1];
    #pragma unroll 4
    for (int o = 0; o < HID; o++) {
        float p = g_pooled[g * HID + o] * inv;
        l0 += p * Wout[o];
        l1 += p * Wout[HID + o];
    }
    float m = fmaxf(l0, l1);
    float lse = m + logf(expf(l0 - m) + expf(l1 - m));
    out[g * 2 + 0] = l0 - lse;
    out[g * 2 + 1] = l1 - lse;
}

// ---------------- launch ----------------
extern "C" void kernel_launch(void* const* d_in, const int* in_sizes, int n_in,
                              void* d_out, int out_size) {
    const float* x     = (const float*)d_in[0];
    const int*   ei    = (const int*)d_in[1];
    const int*   batch = (const int*)d_in[2];
    const float* Wl1   = (const float*)d_in[3];
    const float* bl1   = (const float*)d_in[4];
    const float* Wr1   = (const float*)d_in[5];
    const float* Wl2   = (const float*)d_in[6];
    const float* bl2   = (const float*)d_in[7];
    const float* Wr2   = (const float*)d_in[8];
    const float* Wout  = (const float*)d_in[9];
    const float* bout  = (const float*)d_in[10];
    float* out = (float*)d_out;

    cudaFuncSetAttribute(mm_mma<0>, cudaFuncAttributeMaxDynamicSharedMemorySize, MM_SMEM);
    cudaFuncSetAttribute(mm_mma<1>, cudaFuncAttributeMaxDynamicSharedMemorySize, MM_SMEM);

    zero_k<<<(N_NODES + 255) / 256, 256>>>();
    count_k<<<(N_EDGES + 255) / 256, 256>>>(ei);
    scan1_k<<<SCAN_B, 1024>>>();
    scan2_k<<<1, 128>>>();
    scan3_k<<<(N_NODES + 255) / 256, 256>>>();
    scatter_k<<<(N_EDGES + 255) / 256, 256>>>(ei);

    xcvt_k<<<(N_NODES * IN_CH / 4 + 255) / 256, 256>>>((const float4*)x);
    wcvt_k<<<(HID * HID + 255) / 256, 256>>>(Wl1, Wr1, Wl2, Wr2);

    const int MMG = (N_NODES + 127) / 128;
    // conv1
    agg64_k<<<(N_NODES + 7) / 8, 256>>>(x);
    mm_mma<0><<<MMG, 256, MM_SMEM>>>(bl1);
    // conv2
    agg128_k<<<(N_NODES + 7) / 8, 256>>>();
    mm_mma<1><<<MMG, 256, MM_SMEM>>>(bl2);

    pool_k<<<N_GRAPHS, 128>>>(batch);
    final_k<<<1, 256>>>(Wout, bout, out);
}

// round 7
// speedup vs baseline: 2.4056x; 1.0752x over previous
#include <cuda_runtime.h>
#include <cuda_bf16.h>
#include <math.h>
#include <stdint.h>

#define N_NODES  100000
#define N_EDGES  1000000
#define IN_CH    64
#define HID      128
#define N_GRAPHS 256
#define SCAN_B   ((N_NODES + 1023) / 1024)   // 98

// ---------------- scratch (static device globals; no allocation) ----------------
__device__ int   g_deg[N_NODES];
__device__ int   g_offs[N_NODES + 1];
__device__ int   g_bsum[128];
__device__ int   g_cur[N_NODES];
__device__ int   g_csr[N_EDGES];
__device__ __align__(16) float g_agg[(size_t)N_NODES * HID];   // tf32-valued
__device__ __align__(16) float g_h1[(size_t)N_NODES * HID];    // tf32-valued (mm B operand)
__device__ __align__(16) __nv_bfloat16 g_h1bf[(size_t)N_NODES * HID];  // agg input
__device__ __align__(16) __nv_bfloat16 g_h2bf[(size_t)N_NODES * HID];  // pool input
__device__ __align__(16) float g_xtf[(size_t)N_NODES * IN_CH];          // mm B operand
__device__ __align__(16) __nv_bfloat16 g_xbf[(size_t)N_NODES * IN_CH]; // agg input
__device__ __align__(16) float g_wl1[HID * IN_CH];
__device__ __align__(16) float g_wr1[HID * IN_CH];
__device__ __align__(16) float g_wl2[HID * HID];
__device__ __align__(16) float g_wr2[HID * HID];
__device__ float g_pooled[N_GRAPHS * HID];
__device__ float g_cnt[N_GRAPHS];

// ---------------- helpers ----------------
__device__ __forceinline__ uint32_t smem_u32(const void* p) {
    uint32_t a;
    asm("{ .reg .u64 t; cvta.to.shared.u64 t, %1; cvt.u32.u64 %0, t; }" : "=r"(a) : "l"(p));
    return a;
}
__device__ __forceinline__ uint32_t f2tf(float f) {
    uint32_t u;
    asm("cvt.rna.tf32.f32 %0, %1;" : "=r"(u) : "f"(f));
    return u;
}
__device__ __forceinline__ float tfv(float f) { return __uint_as_float(f2tf(f)); }

__device__ __forceinline__ void mma_tf32(float* c, const uint32_t* a, const uint32_t* b) {
    asm volatile(
        "mma.sync.aligned.m16n8k8.row.col.f32.tf32.tf32.f32 "
        "{%0,%1,%2,%3}, {%4,%5,%6,%7}, {%8,%9}, {%0,%1,%2,%3};"
        : "+f"(c[0]), "+f"(c[1]), "+f"(c[2]), "+f"(c[3])
        : "r"(a[0]), "r"(a[1]), "r"(a[2]), "r"(a[3]), "r"(b[0]), "r"(b[1]));
}
__device__ __forceinline__ void cp16(uint32_t dst, const void* src) {
    asm volatile("cp.async.cg.shared.global [%0], [%1], 16;" :: "r"(dst), "l"(src));
}
__device__ __forceinline__ void cp16p(uint32_t dst, const void* src, bool full) {
    int sz = full ? 16 : 0;
    asm volatile("cp.async.cg.shared.global [%0], [%1], 16, %2;" :: "r"(dst), "l"(src), "r"(sz));
}
#define CP_COMMIT() asm volatile("cp.async.commit_group;" ::: "memory")
#define CP_WAIT1()  asm volatile("cp.async.wait_group 1;" ::: "memory")
#define CP_WAIT0()  asm volatile("cp.async.wait_group 0;" ::: "memory")

// ---------------- fused init: zero deg + tf32/bf16 conversions ----------------
__global__ void init_k(const float4* __restrict__ x,
                       const float* __restrict__ wl1, const float* __restrict__ wr1,
                       const float* __restrict__ wl2, const float* __restrict__ wr2) {
    int i = blockIdx.x * blockDim.x + threadIdx.x;
    if (i < N_NODES) g_deg[i] = 0;
    if (i < HID * IN_CH) { g_wl1[i] = tfv(wl1[i]); g_wr1[i] = tfv(wr1[i]); }
    if (i < HID * HID)   { g_wl2[i] = tfv(wl2[i]); g_wr2[i] = tfv(wr2[i]); }
    if (i < N_NODES * IN_CH / 4) {
        float4 v = x[i];
        float4 o;
        o.x = tfv(v.x); o.y = tfv(v.y); o.z = tfv(v.z); o.w = tfv(v.w);
        *((float4*)g_xtf + i) = o;
        __nv_bfloat162 p0 = __floats2bfloat162_rn(v.x, v.y);
        __nv_bfloat162 p1 = __floats2bfloat162_rn(v.z, v.w);
        uint2 pk;
        pk.x = *(uint32_t*)&p0;
        pk.y = *(uint32_t*)&p1;
        *((uint2*)g_xbf + i) = pk;
    }
}

// ---------------- CSR build ----------------
__global__ void count_k(const int* __restrict__ ei) {
    int e = blockIdx.x * blockDim.x + threadIdx.x;
    if (e < N_EDGES) atomicAdd(&g_deg[ei[N_EDGES + e]], 1);
}

__global__ void scan1_k() {
    __shared__ int s[1024];
    int i = blockIdx.x * 1024 + threadIdx.x;
    int v = (i < N_NODES) ? g_deg[i] : 0;
    s[threadIdx.x] = v;
    __syncthreads();
    #pragma unroll
    for (int off = 1; off < 1024; off <<= 1) {
        int t = (threadIdx.x >= off) ? s[threadIdx.x - off] : 0;
        __syncthreads();
        s[threadIdx.x] += t;
        __syncthreads();
    }
    if (i < N_NODES) g_offs[i] = s[threadIdx.x] - v;   // exclusive within block
    if (threadIdx.x == 1023) g_bsum[blockIdx.x] = s[1023];
}

// scan3 with block-local re-scan of the 98 block sums (eliminates scan2 launch)
__global__ void scan3_k() {
    __shared__ int s[128];
    int t = threadIdx.x;
    int v = 0;
    if (t < 128) { v = (t < SCAN_B) ? g_bsum[t] : 0; s[t] = v; }
    __syncthreads();
    #pragma unroll
    for (int off = 1; off < 128; off <<= 1) {
        int u = (t >= off && t < 128) ? s[t - off] : 0;
        __syncthreads();
        if (t < 128) s[t] += u;
        __syncthreads();
    }
    if (t < 128) s[t] -= v;   // exclusive prefix of block sums
    __syncthreads();
    int i = blockIdx.x * blockDim.x + t;
    if (i < N_NODES) {
        int val = g_offs[i] + s[i >> 10];
        g_offs[i] = val;
        g_cur[i]  = val;
    }
    if (i == 0) g_offs[N_NODES] = N_EDGES;
}

__global__ void scatter_k(const int* __restrict__ ei) {
    int e = blockIdx.x * blockDim.x + threadIdx.x;
    if (e < N_EDGES) {
        int d = ei[N_EDGES + e];
        int slot = atomicAdd(&g_cur[d], 1);
        g_csr[slot] = ei[e];
    }
}

// ---------------- mean aggregation (warp per node, bf16 gather) ----------------
__global__ void agg64_k() {
    int node = (blockIdx.x * blockDim.x + threadIdx.x) >> 5;
    int lane = threadIdx.x & 31;
    if (node >= N_NODES) return;
    int beg = g_offs[node], end = g_offs[node + 1];
    float2 a0 = make_float2(0.f, 0.f), a1 = make_float2(0.f, 0.f);
    int j = beg;
    for (; j + 1 < end; j += 2) {
        int s0 = g_csr[j], s1 = g_csr[j + 1];
        uint32_t p0 = __ldg((const uint32_t*)(g_xbf + (size_t)s0 * IN_CH) + lane);
        uint32_t p1 = __ldg((const uint32_t*)(g_xbf + (size_t)s1 * IN_CH) + lane);
        float2 v0 = __bfloat1622float2(*(__nv_bfloat162*)&p0);
        float2 v1 = __bfloat1622float2(*(__nv_bfloat162*)&p1);
        a0.x += v0.x; a0.y += v0.y;
        a1.x += v1.x; a1.y += v1.y;
    }
    if (j < end) {
        int s0 = g_csr[j];
        uint32_t p0 = __ldg((const uint32_t*)(g_xbf + (size_t)s0 * IN_CH) + lane);
        float2 v0 = __bfloat1622float2(*(__nv_bfloat162*)&p0);
        a0.x += v0.x; a0.y += v0.y;
    }
    float inv = 1.f / (float)max(end - beg, 1);
    float2 o;
    o.x = tfv((a0.x + a1.x) * inv);
    o.y = tfv((a0.y + a1.y) * inv);
    *((float2*)(g_agg + (size_t)node * IN_CH) + lane) = o;
}

__global__ void agg128_k() {
    int node = (blockIdx.x * blockDim.x + threadIdx.x) >> 5;
    int lane = threadIdx.x & 31;
    if (node >= N_NODES) return;
    int beg = g_offs[node], end = g_offs[node + 1];
    float4 a0 = make_float4(0.f, 0.f, 0.f, 0.f), a1 = make_float4(0.f, 0.f, 0.f, 0.f);
    int j = beg;
    for (; j + 1 < end; j += 2) {
        int s0 = g_csr[j], s1 = g_csr[j + 1];
        uint2 p0 = __ldg((const uint2*)(g_h1bf + (size_t)s0 * HID) + lane);
        uint2 p1 = __ldg((const uint2*)(g_h1bf + (size_t)s1 * HID) + lane);
        float2 v00 = __bfloat1622float2(*(__nv_bfloat162*)&p0.x);
        float2 v01 = __bfloat1622float2(*(__nv_bfloat162*)&p0.y);
        float2 v10 = __bfloat1622float2(*(__nv_bfloat162*)&p1.x);
        float2 v11 = __bfloat1622float2(*(__nv_bfloat162*)&p1.y);
        a0.x += v00.x; a0.y += v00.y; a0.z += v01.x; a0.w += v01.y;
        a1.x += v10.x; a1.y += v10.y; a1.z += v11.x; a1.w += v11.y;
    }
    if (j < end) {
        int s0 = g_csr[j];
        uint2 p0 = __ldg((const uint2*)(g_h1bf + (size_t)s0 * HID) + lane);
        float2 v00 = __bfloat1622float2(*(__nv_bfloat162*)&p0.x);
        float2 v01 = __bfloat1622float2(*(__nv_bfloat162*)&p0.y);
        a0.x += v00.x; a0.y += v00.y; a0.z += v01.x; a0.w += v01.y;
    }
    float inv = 1.f / (float)max(end - beg, 1);
    float4 o;
    o.x = tfv((a0.x + a1.x) * inv);
    o.y = tfv((a0.y + a1.y) * inv);
    o.z = tfv((a0.z + a1.z) * inv);
    o.w = tfv((a0.w + a1.w) * inv);
    *((float4*)(g_agg + (size_t)node * HID) + lane) = o;
}

// ---------------- tf32 mma.sync fused SAGE matmul (cp.async double-buffered) ----
#define SSTR 36
#define MMTILE (128 * SSTR)
#define MMBUF  (2 * MMTILE)
#define MM_SMEM (2 * MMBUF * 4)    // 73728 bytes

__device__ __forceinline__ void mm_stage(uint32_t sbase, int buf, int tid, int nbase,
                                         const float* M, const float* W, int K, int kb) {
    #pragma unroll
    for (int i = 0; i < 4; i++) {
        int f = tid + i * 256;
        int row = f >> 3, c4 = (f & 7) * 4;
        uint32_t da = sbase + (uint32_t)(buf * MMBUF + row * SSTR + c4) * 4u;
        int grow = nbase + row;
        cp16p(da, M + (size_t)grow * K + kb + c4, grow < N_NODES);
        cp16(da + MMTILE * 4u, W + (size_t)row * K + kb + c4);
    }
    CP_COMMIT();
}

__device__ __forceinline__ void mm_compute(const uint32_t* sbuf, int warp_m, int warp_n,
                                           int g, int tig, float acc[4][4][4]) {
    const uint32_t* sA = sbuf;
    const uint32_t* sW = sbuf + MMTILE;
    #pragma unroll
    for (int ks = 0; ks < 4; ks++) {
        int k0 = ks * 8;
        uint32_t af[4][4], bf[4][2];
        #pragma unroll
        for (int mt = 0; mt < 4; mt++) {
            int r0 = warp_m + mt * 16;
            af[mt][0] = sA[(r0 + g) * SSTR + k0 + tig];
            af[mt][1] = sA[(r0 + g + 8) * SSTR + k0 + tig];
            af[mt][2] = sA[(r0 + g) * SSTR + k0 + tig + 4];
            af[mt][3] = sA[(r0 + g + 8) * SSTR + k0 + tig + 4];
        }
        #pragma unroll
        for (int nt = 0; nt < 4; nt++) {
            int c0 = warp_n + nt * 8;
            bf[nt][0] = sW[(c0 + g) * SSTR + k0 + tig];
            bf[nt][1] = sW[(c0 + g) * SSTR + k0 + tig + 4];
        }
        #pragma unroll
        for (int mt = 0; mt < 4; mt++)
            #pragma unroll
            for (int nt = 0; nt < 4; nt++)
                mma_tf32(acc[mt][nt], af[mt], bf[nt]);
    }
}

template<int LAYER>
__global__ __launch_bounds__(256, 2) void mm_mma(const float* __restrict__ bias) {
    extern __shared__ uint32_t dsm[];
    __shared__ float sBias[128];

    const float* A  = (const float*)g_agg;
    const float* B  = (LAYER == 0) ? (const float*)g_xtf : (const float*)g_h1;
    const float* Wa = (LAYER == 0) ? (const float*)g_wl1 : (const float*)g_wl2;
    const float* Wb = (LAYER == 0) ? (const float*)g_wr1 : (const float*)g_wr2;
    constexpr int K = (LAYER == 0) ? IN_CH : HID;
    constexpr int nA = K / 32;
    constexpr int total = 2 * nA;

    int tid = threadIdx.x, wid = tid >> 5, lane = tid & 31;
    int g = lane >> 2, tig = lane & 3;
    int warp_m = (wid & 1) * 64;
    int warp_n = (wid >> 1) * 32;
    int nbase = blockIdx.x * 128;
    uint32_t sbase = smem_u32(dsm);

    if (tid < 128) sBias[tid] = bias[tid];

    float acc[4][4][4];
    #pragma unroll
    for (int mt = 0; mt < 4; mt++)
        #pragma unroll
        for (int nt = 0; nt < 4; nt++)
            #pragma unroll
            for (int r = 0; r < 4; r++) acc[mt][nt][r] = 0.f;

    auto pick = [&](int c, const float*& M, const float*& W, int& kb) {
        if (c < nA) { M = A; W = Wa; kb = c * 32; }
        else        { M = B; W = Wb; kb = (c - nA) * 32; }
    };

    { const float* M; const float* W; int kb;
      pick(0, M, W, kb);
      mm_stage(sbase, 0, tid, nbase, M, W, K, kb); }

    #pragma unroll 1
    for (int c = 0; c < total; c++) {
        if (c + 1 < total) {
            const float* M; const float* W; int kb;
            pick(c + 1, M, W, kb);
            mm_stage(sbase, (c + 1) & 1, tid, nbase, M, W, K, kb);
            CP_WAIT1();
        } else {
            CP_WAIT0();
        }
        __syncthreads();
        mm_compute(dsm + (c & 1) * MMBUF, warp_m, warp_n, g, tig, acc);
        __syncthreads();
    }

    // epilogue: bias + relu
    // LAYER 0: store tf32 fp32 h1 (mm B operand) + bf16 h1 (agg input)
    // LAYER 1: store bf16 h2 only (pool input)
    #pragma unroll
    for (int mt = 0; mt < 4; mt++) {
        #pragma unroll
        for (int half = 0; half < 2; half++) {
            int row = nbase + warp_m + mt * 16 + g + half * 8;
            if (row < N_NODES) {
                #pragma unroll
                for (int nt = 0; nt < 4; nt++) {
                    int col = warp_n + nt * 8 + 2 * tig;
                    float vx = fmaxf(acc[mt][nt][half * 2 + 0] + sBias[col + 0], 0.f);
                    float vy = fmaxf(acc[mt][nt][half * 2 + 1] + sBias[col + 1], 0.f);
                    __nv_bfloat162 pb = __floats2bfloat162_rn(vx, vy);
                    if (LAYER == 0) {
                        float2 v; v.x = tfv(vx); v.y = tfv(vy);
                        *(float2*)(g_h1 + (size_t)row * HID + col) = v;
                        *(__nv_bfloat162*)(g_h1bf + (size_t)row * HID + col) = pb;
                    } else {
                        *(__nv_bfloat162*)(g_h2bf + (size_t)row * HID + col) = pb;
                    }
                }
            }
        }
    }
}

// ---------------- per-graph mean pool (batch is sorted, bf16 input) ------------
__global__ void pool_k(const int* __restrict__ batch) {
    int g = blockIdx.x;
    __shared__ int s_lo, s_hi;
    if (threadIdx.x == 0) {
        int a = 0, b = N_NODES;
        while (a < b) { int m = (a + b) >> 1; if (batch[m] < g) a = m + 1; else b = m; }
        s_lo = a;
        b = N_NODES;
        while (a < b) { int m = (a + b) >> 1; if (batch[m] < g + 1) a = m + 1; else b = m; }
        s_hi = a;
    }
    __syncthreads();
    int lo = s_lo, hi = s_hi;
    int half = threadIdx.x;   // 64 threads, each owns 2 cols via bf16x2
    float2 acc = make_float2(0.f, 0.f);
    for (int r = lo; r < hi; r++) {
        uint32_t p = __ldg((const uint32_t*)(g_h2bf + (size_t)r * HID) + half);
        float2 v = __bfloat1622float2(*(__nv_bfloat162*)&p);
        acc.x += v.x; acc.y += v.y;
    }
    g_pooled[g * HID + 2 * half + 0] = acc.x;
    g_pooled[g * HID + 2 * half + 1] = acc.y;
    if (threadIdx.x == 0) g_cnt[g] = (float)(hi - lo);
}

// ---------------- head: normalize + linear + log_softmax ----------------
__global__ void final_k(const float* __restrict__ Wout,
                        const float* __restrict__ bout,
                        float* __restrict__ out) {
    int g = threadIdx.x + blockIdx.x * blockDim.x;
    if (g >= N_GRAPHS) return;
    float inv = 1.f / fmaxf(g_cnt[g], 1.f);
    float l0 = bout[0], l1 = bout[1];
    #pragma unroll 4
    for (int o = 0; o < HID; o++) {
        float p = g_pooled[g * HID + o] * inv;
        l0 += p * Wout[o];
        l1 += p * Wout[HID + o];
    }
    float m = fmaxf(l0, l1);
    float lse = m + logf(expf(l0 - m) + expf(l1 - m));
    out[g * 2 + 0] = l0 - lse;
    out[g * 2 + 1] = l1 - lse;
}

// ---------------- launch ----------------
extern "C" void kernel_launch(void* const* d_in, const int* in_sizes, int n_in,
                              void* d_out, int out_size) {
    const float* x     = (const float*)d_in[0];
    const int*   ei    = (const int*)d_in[1];
    const int*   batch = (const int*)d_in[2];
    const float* Wl1   = (const float*)d_in[3];
    const float* bl1   = (const float*)d_in[4];
    const float* Wr1   = (const float*)d_in[5];
    const float* Wl2   = (const float*)d_in[6];
    const float* bl2   = (const float*)d_in[7];
    const float* Wr2   = (const float*)d_in[8];
    const float* Wout  = (const float*)d_in[9];
    const float* bout  = (const float*)d_in[10];
    float* out = (float*)d_out;

    cudaFuncSetAttribute(mm_mma<0>, cudaFuncAttributeMaxDynamicSharedMemorySize, MM_SMEM);
    cudaFuncSetAttribute(mm_mma<1>, cudaFuncAttributeMaxDynamicSharedMemorySize, MM_SMEM);

    init_k<<<(N_NODES * IN_CH / 4 + 255) / 256, 256>>>((const float4*)x, Wl1, Wr1, Wl2, Wr2);
    count_k<<<(N_EDGES + 255) / 256, 256>>>(ei);
    scan1_k<<<SCAN_B, 1024>>>();
    scan3_k<<<(N_NODES + 255) / 256, 256>>>();
    scatter_k<<<(N_EDGES + 255) / 256, 256>>>(ei);

    const int MMG = (N_NODES + 127) / 128;
    // conv1
    agg64_k<<<(N_NODES + 7) / 8, 256>>>();
    mm_mma<0><<<MMG, 256, MM_SMEM>>>(bl1);
    // conv2
    agg128_k<<<(N_NODES + 7) / 8, 256>>>();
    mm_mma<1><<<MMG, 256, MM_SMEM>>>(bl2);

    pool_k<<<N_GRAPHS, 64>>>(batch);
    final_k<<<1, 256>>>(Wout, bout, out);
}

// round 8
// speedup vs baseline: 2.9539x; 1.2279x over previous
#include <cuda_runtime.h>
#include <cuda_bf16.h>
#include <math.h>
#include <stdint.h>

#define N_NODES  100000
#define N_EDGES  1000000
#define IN_CH    64
#define HID      128
#define N_GRAPHS 256
#define SCAN_B   ((N_NODES + 1023) / 1024)   // 98

// ---------------- scratch (static device globals; no allocation) ----------------
__device__ int   g_deg[N_NODES];
__device__ int   g_offs[N_NODES + 1];
__device__ int   g_bsum[128];
__device__ int   g_cur[N_NODES];
__device__ int   g_csr[N_EDGES];
__device__ __align__(16) __nv_bfloat16 g_aggbf[(size_t)N_NODES * HID]; // mean-agg (bf16)
__device__ __align__(16) __nv_bfloat16 g_xbf[(size_t)N_NODES * IN_CH]; // x (bf16)
__device__ __align__(16) __nv_bfloat16 g_h1bf[(size_t)N_NODES * HID];  // h1 (bf16)
__device__ __align__(16) __nv_bfloat16 g_h2bf[(size_t)N_NODES * HID];  // h2 (bf16)
__device__ __align__(16) float g_wl1[HID * IN_CH];   // tf32-valued weights
__device__ __align__(16) float g_wr1[HID * IN_CH];
__device__ __align__(16) float g_wl2[HID * HID];
__device__ __align__(16) float g_wr2[HID * HID];

// ---------------- helpers ----------------
__device__ __forceinline__ uint32_t smem_u32(const void* p) {
    uint32_t a;
    asm("{ .reg .u64 t; cvta.to.shared.u64 t, %1; cvt.u32.u64 %0, t; }" : "=r"(a) : "l"(p));
    return a;
}
__device__ __forceinline__ uint32_t f2tf(float f) {
    uint32_t u;
    asm("cvt.rna.tf32.f32 %0, %1;" : "=r"(u) : "f"(f));
    return u;
}
__device__ __forceinline__ float tfv(float f) { return __uint_as_float(f2tf(f)); }
// bf16 half of a packed pair -> fp32 bit pattern (exact; valid tf32 operand)
__device__ __forceinline__ uint32_t bfhalf(uint32_t pair, int hi) {
    return hi ? (pair & 0xFFFF0000u) : (pair << 16);
}

__device__ __forceinline__ void mma_tf32(float* c, const uint32_t* a, const uint32_t* b) {
    asm volatile(
        "mma.sync.aligned.m16n8k8.row.col.f32.tf32.tf32.f32 "
        "{%0,%1,%2,%3}, {%4,%5,%6,%7}, {%8,%9}, {%0,%1,%2,%3};"
        : "+f"(c[0]), "+f"(c[1]), "+f"(c[2]), "+f"(c[3])
        : "r"(a[0]), "r"(a[1]), "r"(a[2]), "r"(a[3]), "r"(b[0]), "r"(b[1]));
}
__device__ __forceinline__ void cp16(uint32_t dst, const void* src) {
    asm volatile("cp.async.cg.shared.global [%0], [%1], 16;" :: "r"(dst), "l"(src));
}
__device__ __forceinline__ void cp16p(uint32_t dst, const void* src, bool full) {
    int sz = full ? 16 : 0;
    asm volatile("cp.async.cg.shared.global [%0], [%1], 16, %2;" :: "r"(dst), "l"(src), "r"(sz));
}
#define CP_COMMIT() asm volatile("cp.async.commit_group;" ::: "memory")
#define CP_WAIT1()  asm volatile("cp.async.wait_group 1;" ::: "memory")
#define CP_WAIT0()  asm volatile("cp.async.wait_group 0;" ::: "memory")

// ---------------- fused init: zero deg + weight tf32 cvt + x bf16 cvt ----------
__global__ void init_k(const float4* __restrict__ x,
                       const float* __restrict__ wl1, const float* __restrict__ wr1,
                       const float* __restrict__ wl2, const float* __restrict__ wr2) {
    int i = blockIdx.x * blockDim.x + threadIdx.x;
    if (i < N_NODES) g_deg[i] = 0;
    if (i < HID * IN_CH) { g_wl1[i] = tfv(wl1[i]); g_wr1[i] = tfv(wr1[i]); }
    if (i < HID * HID)   { g_wl2[i] = tfv(wl2[i]); g_wr2[i] = tfv(wr2[i]); }
    if (i < N_NODES * IN_CH / 4) {
        float4 v = x[i];
        __nv_bfloat162 p0 = __floats2bfloat162_rn(v.x, v.y);
        __nv_bfloat162 p1 = __floats2bfloat162_rn(v.z, v.w);
        uint2 pk;
        pk.x = *(uint32_t*)&p0;
        pk.y = *(uint32_t*)&p1;
        *((uint2*)g_xbf + i) = pk;
    }
}

// ---------------- CSR build ----------------
__global__ void count_k(const int* __restrict__ ei) {
    int e = blockIdx.x * blockDim.x + threadIdx.x;
    if (e < N_EDGES) atomicAdd(&g_deg[ei[N_EDGES + e]], 1);
}

__global__ void scan1_k() {
    __shared__ int s[1024];
    int i = blockIdx.x * 1024 + threadIdx.x;
    int v = (i < N_NODES) ? g_deg[i] : 0;
    s[threadIdx.x] = v;
    __syncthreads();
    #pragma unroll
    for (int off = 1; off < 1024; off <<= 1) {
        int t = (threadIdx.x >= off) ? s[threadIdx.x - off] : 0;
        __syncthreads();
        s[threadIdx.x] += t;
        __syncthreads();
    }
    if (i < N_NODES) g_offs[i] = s[threadIdx.x] - v;   // exclusive within block
    if (threadIdx.x == 1023) g_bsum[blockIdx.x] = s[1023];
}

// scan3 with block-local re-scan of the 98 block sums (no separate scan2 launch)
__global__ void scan3_k() {
    __shared__ int s[128];
    int t = threadIdx.x;
    int v = 0;
    if (t < 128) { v = (t < SCAN_B) ? g_bsum[t] : 0; s[t] = v; }
    __syncthreads();
    #pragma unroll
    for (int off = 1; off < 128; off <<= 1) {
        int u = (t >= off && t < 128) ? s[t - off] : 0;
        __syncthreads();
        if (t < 128) s[t] += u;
        __syncthreads();
    }
    if (t < 128) s[t] -= v;   // exclusive prefix of block sums
    __syncthreads();
    int i = blockIdx.x * blockDim.x + t;
    if (i < N_NODES) {
        int val = g_offs[i] + s[i >> 10];
        g_offs[i] = val;
        g_cur[i]  = val;
    }
    if (i == 0) g_offs[N_NODES] = N_EDGES;
}

__global__ void scatter_k(const int* __restrict__ ei) {
    int e = blockIdx.x * blockDim.x + threadIdx.x;
    if (e < N_EDGES) {
        int d = ei[N_EDGES + e];
        int slot = atomicAdd(&g_cur[d], 1);
        g_csr[slot] = ei[e];
    }
}

// ---------------- mean aggregation (warp per node, bf16 gather, bf16 store) ----
__global__ void agg64_k() {
    int node = (blockIdx.x * blockDim.x + threadIdx.x) >> 5;
    int lane = threadIdx.x & 31;
    if (node >= N_NODES) return;
    int beg = g_offs[node], end = g_offs[node + 1];
    float2 a0 = make_float2(0.f, 0.f), a1 = make_float2(0.f, 0.f);
    int j = beg;
    for (; j + 1 < end; j += 2) {
        int s0 = g_csr[j], s1 = g_csr[j + 1];
        uint32_t p0 = __ldg((const uint32_t*)(g_xbf + (size_t)s0 * IN_CH) + lane);
        uint32_t p1 = __ldg((const uint32_t*)(g_xbf + (size_t)s1 * IN_CH) + lane);
        float2 v0 = __bfloat1622float2(*(__nv_bfloat162*)&p0);
        float2 v1 = __bfloat1622float2(*(__nv_bfloat162*)&p1);
        a0.x += v0.x; a0.y += v0.y;
        a1.x += v1.x; a1.y += v1.y;
    }
    if (j < end) {
        int s0 = g_csr[j];
        uint32_t p0 = __ldg((const uint32_t*)(g_xbf + (size_t)s0 * IN_CH) + lane);
        float2 v0 = __bfloat1622float2(*(__nv_bfloat162*)&p0);
        a0.x += v0.x; a0.y += v0.y;
    }
    float inv = 1.f / (float)max(end - beg, 1);
    __nv_bfloat162 o = __floats2bfloat162_rn((a0.x + a1.x) * inv, (a0.y + a1.y) * inv);
    ((uint32_t*)(g_aggbf + (size_t)node * IN_CH))[lane] = *(uint32_t*)&o;
}

__global__ void agg128_k() {
    int node = (blockIdx.x * blockDim.x + threadIdx.x) >> 5;
    int lane = threadIdx.x & 31;
    if (node >= N_NODES) return;
    int beg = g_offs[node], end = g_offs[node + 1];
    float4 a0 = make_float4(0.f, 0.f, 0.f, 0.f), a1 = make_float4(0.f, 0.f, 0.f, 0.f);
    int j = beg;
    for (; j + 1 < end; j += 2) {
        int s0 = g_csr[j], s1 = g_csr[j + 1];
        uint2 p0 = __ldg((const uint2*)(g_h1bf + (size_t)s0 * HID) + lane);
        uint2 p1 = __ldg((const uint2*)(g_h1bf + (size_t)s1 * HID) + lane);
        float2 v00 = __bfloat1622float2(*(__nv_bfloat162*)&p0.x);
        float2 v01 = __bfloat1622float2(*(__nv_bfloat162*)&p0.y);
        float2 v10 = __bfloat1622float2(*(__nv_bfloat162*)&p1.x);
        float2 v11 = __bfloat1622float2(*(__nv_bfloat162*)&p1.y);
        a0.x += v00.x; a0.y += v00.y; a0.z += v01.x; a0.w += v01.y;
        a1.x += v10.x; a1.y += v10.y; a1.z += v11.x; a1.w += v11.y;
    }
    if (j < end) {
        int s0 = g_csr[j];
        uint2 p0 = __ldg((const uint2*)(g_h1bf + (size_t)s0 * HID) + lane);
        float2 v00 = __bfloat1622float2(*(__nv_bfloat162*)&p0.x);
        float2 v01 = __bfloat1622float2(*(__nv_bfloat162*)&p0.y);
        a0.x += v00.x; a0.y += v00.y; a0.z += v01.x; a0.w += v01.y;
    }
    float inv = 1.f / (float)max(end - beg, 1);
    __nv_bfloat162 o0 = __floats2bfloat162_rn((a0.x + a1.x) * inv, (a0.y + a1.y) * inv);
    __nv_bfloat162 o1 = __floats2bfloat162_rn((a0.z + a1.z) * inv, (a0.w + a1.w) * inv);
    uint2 pk;
    pk.x = *(uint32_t*)&o0;
    pk.y = *(uint32_t*)&o1;
    ((uint2*)(g_aggbf + (size_t)node * HID))[lane] = pk;
}

// ---------------- tf32 mma.sync fused SAGE matmul -------------------------------
// Features (A: agg, B: x/h1) staged as bf16 (half traffic); W staged as tf32 fp32.
// bf16 -> fp32 at fragment load is an exact shift; MMA stays tf32.
#define FSTR 20                     // uint32 words per feature row (16B-aligned, conflict-free)
#define FTILE (128 * FSTR)          // 2560 words
#define SSTR 36
#define WTILE (128 * SSTR)          // 4608 words
#define MMBUF (FTILE + WTILE)       // 7168 words
#define MM_SMEM (2 * MMBUF * 4)     // 57344 bytes

__device__ __forceinline__ void mm_stage(uint32_t sbase, int buf, int tid, int nbase,
                                         const __nv_bfloat16* F, const float* W,
                                         int K, int kb) {
    // feature tile: 128 rows x 32 bf16 = 64B/row = 4 x 16B segs; 512 segs / 256 thr
    #pragma unroll
    for (int i = 0; i < 2; i++) {
        int f = tid + i * 256;
        int row = f >> 2, s = f & 3;
        uint32_t da = sbase + (uint32_t)(buf * MMBUF + row * FSTR + 4 * s) * 4u;
        int grow = nbase + row;
        cp16p(da, F + (size_t)grow * K + kb + 8 * s, grow < N_NODES);
    }
    // weight tile: 128 rows x 32 fp32 = 128B/row = 8 x 16B segs; 1024 / 256 thr
    #pragma unroll
    for (int i = 0; i < 4; i++) {
        int f = tid + i * 256;
        int row = f >> 3, c4 = (f & 7) * 4;
        uint32_t da = sbase + (uint32_t)(buf * MMBUF + FTILE + row * SSTR + c4) * 4u;
        cp16(da, W + (size_t)row * K + kb + c4);
    }
    CP_COMMIT();
}

__device__ __forceinline__ void mm_compute(const uint32_t* sbuf, int warp_m, int warp_n,
                                           int g, int tig, float acc[4][4][4]) {
    const uint32_t* sF = sbuf;
    const uint32_t* sW = sbuf + FTILE;
    int hi = tig & 1;
    #pragma unroll
    for (int ks = 0; ks < 4; ks++) {
        int k0 = ks * 8;
        int wb = 4 * ks + (tig >> 1);
        uint32_t af[4][4], bf[4][2];
        #pragma unroll
        for (int mt = 0; mt < 4; mt++) {
            const uint32_t* r0p = sF + (warp_m + mt * 16 + g) * FSTR;
            const uint32_t* r1p = r0p + 8 * FSTR;
            af[mt][0] = bfhalf(r0p[wb], hi);
            af[mt][1] = bfhalf(r1p[wb], hi);
            af[mt][2] = bfhalf(r0p[wb + 2], hi);
            af[mt][3] = bfhalf(r1p[wb + 2], hi);
        }
        #pragma unroll
        for (int nt = 0; nt < 4; nt++) {
            int c0 = warp_n + nt * 8;
            bf[nt][0] = sW[(c0 + g) * SSTR + k0 + tig];
            bf[nt][1] = sW[(c0 + g) * SSTR + k0 + tig + 4];
        }
        #pragma unroll
        for (int mt = 0; mt < 4; mt++)
            #pragma unroll
            for (int nt = 0; nt < 4; nt++)
                mma_tf32(acc[mt][nt], af[mt], bf[nt]);
    }
}

template<int LAYER>
__global__ __launch_bounds__(256, 2) void mm_mma(const float* __restrict__ bias) {
    extern __shared__ uint32_t dsm[];
    __shared__ float sBias[128];

    const __nv_bfloat16* A = (const __nv_bfloat16*)g_aggbf;
    const __nv_bfloat16* B = (LAYER == 0) ? (const __nv_bfloat16*)g_xbf
                                          : (const __nv_bfloat16*)g_h1bf;
    const float* Wa = (LAYER == 0) ? (const float*)g_wl1 : (const float*)g_wl2;
    const float* Wb = (LAYER == 0) ? (const float*)g_wr1 : (const float*)g_wr2;
    constexpr int K = (LAYER == 0) ? IN_CH : HID;
    constexpr int nA = K / 32;
    constexpr int total = 2 * nA;

    int tid = threadIdx.x, wid = tid >> 5, lane = tid & 31;
    int g = lane >> 2, tig = lane & 3;
    int warp_m = (wid & 1) * 64;
    int warp_n = (wid >> 1) * 32;
    int nbase = blockIdx.x * 128;
    uint32_t sbase = smem_u32(dsm);

    if (tid < 128) sBias[tid] = bias[tid];

    float acc[4][4][4];
    #pragma unroll
    for (int mt = 0; mt < 4; mt++)
        #pragma unroll
        for (int nt = 0; nt < 4; nt++)
            #pragma unroll
            for (int r = 0; r < 4; r++) acc[mt][nt][r] = 0.f;

    auto pick = [&](int c, const __nv_bfloat16*& F, const float*& W, int& kb) {
        if (c < nA) { F = A; W = Wa; kb = c * 32; }
        else        { F = B; W = Wb; kb = (c - nA) * 32; }
    };

    { const __nv_bfloat16* F; const float* W; int kb;
      pick(0, F, W, kb);
      mm_stage(sbase, 0, tid, nbase, F, W, K, kb); }

    #pragma unroll 1
    for (int c = 0; c < total; c++) {
        if (c + 1 < total) {
            const __nv_bfloat16* F; const float* W; int kb;
            pick(c + 1, F, W, kb);
            mm_stage(sbase, (c + 1) & 1, tid, nbase, F, W, K, kb);
            CP_WAIT1();
        } else {
            CP_WAIT0();
        }
        __syncthreads();
        mm_compute(dsm + (c & 1) * MMBUF, warp_m, warp_n, g, tig, acc);
        __syncthreads();
    }

    // epilogue: bias + relu -> bf16 store only
    __nv_bfloat16* dst = (LAYER == 0) ? (__nv_bfloat16*)g_h1bf : (__nv_bfloat16*)g_h2bf;
    #pragma unroll
    for (int mt = 0; mt < 4; mt++) {
        #pragma unroll
        for (int half = 0; half < 2; half++) {
            int row = nbase + warp_m + mt * 16 + g + half * 8;
            if (row < N_NODES) {
                #pragma unroll
                for (int nt = 0; nt < 4; nt++) {
                    int col = warp_n + nt * 8 + 2 * tig;
                    float vx = fmaxf(acc[mt][nt][half * 2 + 0] + sBias[col + 0], 0.f);
                    float vy = fmaxf(acc[mt][nt][half * 2 + 1] + sBias[col + 1], 0.f);
                    __nv_bfloat162 pb = __floats2bfloat162_rn(vx, vy);
                    *(__nv_bfloat162*)(dst + (size_t)row * HID + col) = pb;
                }
            }
        }
    }
}

// ---------------- fused per-graph mean pool + head (batch is sorted) ------------
// block per graph, 256 threads = 4 row-groups x 64 col-pairs
__global__ void poolfinal_k(const int* __restrict__ batch,
                            const float* __restrict__ Wout,
                            const float* __restrict__ bout,
                            float* __restrict__ out) {
    int gidx = blockIdx.x;
    __shared__ int s_lo, s_hi;
    __shared__ float sacc[4][128];
    __shared__ float sl0[128], sl1[128];
    int tid = threadIdx.x;
    int pair = tid & 63, grp = tid >> 6;

    if (tid == 0) {
        int a = 0, b = N_NODES;
        while (a < b) { int m = (a + b) >> 1; if (batch[m] < gidx) a = m + 1; else b = m; }
        s_lo = a;
        b = N_NODES;
        while (a < b) { int m = (a + b) >> 1; if (batch[m] < gidx + 1) a = m + 1; else b = m; }
        s_hi = a;
    }
    __syncthreads();
    int lo = s_lo, hi = s_hi;

    float2 acc = make_float2(0.f, 0.f);
    for (int r = lo + grp; r < hi; r += 4) {
        uint32_t p = __ldg((const uint32_t*)(g_h2bf + (size_t)r * HID) + pair);
        float2 v = __bfloat1622float2(*(__nv_bfloat162*)&p);
        acc.x += v.x; acc.y += v.y;
    }
    sacc[grp][2 * pair + 0] = acc.x;
    sacc[grp][2 * pair + 1] = acc.y;
    __syncthreads();

    if (tid < 128) {
        float inv = 1.f / fmaxf((float)(hi - lo), 1.f);
        float p = (sacc[0][tid] + sacc[1][tid] + sacc[2][tid] + sacc[3][tid]) * inv;
        sl0[tid] = p * Wout[tid];
        sl1[tid] = p * Wout[HID + tid];
    }
    __syncthreads();
    #pragma unroll
    for (int off = 64; off > 0; off >>= 1) {
        if (tid < off) { sl0[tid] += sl0[tid + off]; sl1[tid] += sl1[tid + off]; }
        __syncthreads();
    }
    if (tid == 0) {
        float l0 = sl0[0] + bout[0];
        float l1 = sl1[0] + bout[1];
        float m = fmaxf(l0, l1);
        float lse = m + logf(expf(l0 - m) + expf(l1 - m));
        out[gidx * 2 + 0] = l0 - lse;
        out[gidx * 2 + 1] = l1 - lse;
    }
}

// ---------------- launch ----------------
extern "C" void kernel_launch(void* const* d_in, const int* in_sizes, int n_in,
                              void* d_out, int out_size) {
    const float* x     = (const float*)d_in[0];
    const int*   ei    = (const int*)d_in[1];
    const int*   batch = (const int*)d_in[2];
    const float* Wl1   = (const float*)d_in[3];
    const float* bl1   = (const float*)d_in[4];
    const float* Wr1   = (const float*)d_in[5];
    const float* Wl2   = (const float*)d_in[6];
    const float* bl2   = (const float*)d_in[7];
    const float* Wr2   = (const float*)d_in[8];
    const float* Wout  = (const float*)d_in[9];
    const float* bout  = (const float*)d_in[10];
    float* out = (float*)d_out;

    cudaFuncSetAttribute(mm_mma<0>, cudaFuncAttributeMaxDynamicSharedMemorySize, MM_SMEM);
    cudaFuncSetAttribute(mm_mma<1>, cudaFuncAttributeMaxDynamicSharedMemorySize, MM_SMEM);

    init_k<<<(N_NODES * IN_CH / 4 + 255) / 256, 256>>>((const float4*)x, Wl1, Wr1, Wl2, Wr2);
    count_k<<<(N_EDGES + 255) / 256, 256>>>(ei);
    scan1_k<<<SCAN_B, 1024>>>();
    scan3_k<<<(N_NODES + 255) / 256, 256>>>();
    scatter_k<<<(N_EDGES + 255) / 256, 256>>>(ei);

    const int MMG = (N_NODES + 127) / 128;
    // conv1
    agg64_k<<<(N_NODES + 7) / 8, 256>>>();
    mm_mma<0><<<MMG, 256, MM_SMEM>>>(bl1);
    // conv2
    agg128_k<<<(N_NODES + 7) / 8, 256>>>();
    mm_mma<1><<<MMG, 256, MM_SMEM>>>(bl2);

    poolfinal_k<<<N_GRAPHS, 256>>>(batch, Wout, bout, out);
}